// round 1
// baseline (speedup 1.0000x reference)
#include <cuda_runtime.h>
#include <cstdint>

#define BSZ   2
#define SEQ   2048
#define HID   2048
#define NHEAD 16
#define HDIM  64*2          // 128
#define MROWS (BSZ*SEQ)     // 4096

// ---------------- scratch (static device arrays; no allocation) -------------
__device__ float g_Q[(size_t)MROWS * HID];
__device__ float g_K[(size_t)MROWS * HID];
__device__ float g_V[(size_t)MROWS * HID];
__device__ float g_O[(size_t)MROWS * HID];

// ---------------------------------------------------------------------------
// SGEMM:  C[M,N] = A[M,K] * B[N,K]^T    (both row-major, K contiguous)
// 128x128 tile, BK=16, 256 threads, 8x8 per thread.
// ---------------------------------------------------------------------------
__global__ void __launch_bounds__(256) sgemm_nt(const float* __restrict__ A,
                                                const float* __restrict__ B,
                                                float* __restrict__ C,
                                                int M, int N, int K)
{
    __shared__ float As[16][128];
    __shared__ float Bs[16][128];

    const int tid = threadIdx.x;
    const int tx  = tid & 15;
    const int ty  = tid >> 4;
    const int bm  = blockIdx.y * 128;
    const int bn  = blockIdx.x * 128;

    const int lr = tid >> 2;          // 0..63
    const int lc = (tid & 3) << 2;    // 0,4,8,12

    const float* Ap = A + (size_t)bm * K;
    const float* Bp = B + (size_t)bn * K;

    float acc[8][8];
#pragma unroll
    for (int i = 0; i < 8; ++i)
#pragma unroll
        for (int j = 0; j < 8; ++j) acc[i][j] = 0.f;

    for (int k0 = 0; k0 < K; k0 += 16) {
#pragma unroll
        for (int r = 0; r < 128; r += 64) {
            const int row = lr + r;
            float4 va = *(const float4*)(Ap + (size_t)row * K + k0 + lc);
            As[lc + 0][row] = va.x;
            As[lc + 1][row] = va.y;
            As[lc + 2][row] = va.z;
            As[lc + 3][row] = va.w;
            float4 vb = *(const float4*)(Bp + (size_t)row * K + k0 + lc);
            Bs[lc + 0][row] = vb.x;
            Bs[lc + 1][row] = vb.y;
            Bs[lc + 2][row] = vb.z;
            Bs[lc + 3][row] = vb.w;
        }
        __syncthreads();

#pragma unroll
        for (int kk = 0; kk < 16; ++kk) {
            float a[8], b[8];
            *(float4*)&a[0] = *(const float4*)&As[kk][ty * 8];
            *(float4*)&a[4] = *(const float4*)&As[kk][ty * 8 + 4];
            *(float4*)&b[0] = *(const float4*)&Bs[kk][tx * 8];
            *(float4*)&b[4] = *(const float4*)&Bs[kk][tx * 8 + 4];
#pragma unroll
            for (int i = 0; i < 8; ++i)
#pragma unroll
                for (int j = 0; j < 8; ++j)
                    acc[i][j] += a[i] * b[j];
        }
        __syncthreads();
    }

#pragma unroll
    for (int i = 0; i < 8; ++i) {
        float* Cp = C + (size_t)(bm + ty * 8 + i) * N + bn + tx * 8;
        float4 v0 = make_float4(acc[i][0], acc[i][1], acc[i][2], acc[i][3]);
        float4 v1 = make_float4(acc[i][4], acc[i][5], acc[i][6], acc[i][7]);
        *(float4*)(Cp)     = v0;
        *(float4*)(Cp + 4) = v1;
    }
}

// ---------------------------------------------------------------------------
// RoPE in place on [B,S,H] with per-head dim 128 (half = 64).
// One thread per (b,s,h,j<64) pair.
// ---------------------------------------------------------------------------
__global__ void __launch_bounds__(256) rope_kernel(float* __restrict__ X)
{
    const int i  = blockIdx.x * blockDim.x + threadIdx.x;
    const int j  = i & 63;
    const int t  = i >> 6;
    const int h  = t & (NHEAD - 1);
    const int t2 = t >> 4;
    const int s  = t2 & (SEQ - 1);
    const int b  = t2 >> 11;

    float* p = X + ((size_t)(b * SEQ + s)) * HID + h * HDIM;

    const float invf = powf(10000.0f, -(float)j * (1.0f / 64.0f));
    const float ang  = (float)s * invf;
    float sn, cs;
    sincosf(ang, &sn, &cs);

    const float x1 = p[j];
    const float x2 = p[j + 64];
    p[j]      = x1 * cs - x2 * sn;
    p[j + 64] = x2 * cs + x1 * sn;
}

// ---------------------------------------------------------------------------
// Flash attention (fp32, causal). Block = 256 threads handles one 64-row
// Q tile of one (b,h). Iterates K/V tiles 0..qt with online softmax.
// smem: Qs[64][128], Kt[128][64] (transposed), Vs[64][128], Ps[64][64]
// ---------------------------------------------------------------------------
__global__ void __launch_bounds__(256) flash_kernel(const float* __restrict__ Q,
                                                    const float* __restrict__ K,
                                                    const float* __restrict__ V,
                                                    float* __restrict__ O)
{
    extern __shared__ float sm[];
    float* Qs = sm;               // 64*128
    float* Kt = Qs + 64 * 128;    // 128*64
    float* Vs = Kt + 128 * 64;    // 64*128
    float* Ps = Vs + 64 * 128;    // 64*64

    const int tid = threadIdx.x;
    const int tx  = tid & 15;
    const int ty  = tid >> 4;
    const int qt  = blockIdx.x;
    const int h   = blockIdx.y;
    const int b   = blockIdx.z;

    const size_t base = ((size_t)b * SEQ) * HID + (size_t)h * HDIM;

    // load Q tile
    for (int idx = tid; idx < 64 * 32; idx += 256) {
        const int m  = idx >> 5;
        const int dg = (idx & 31) << 2;
        *(float4*)&Qs[m * 128 + dg] =
            *(const float4*)(Q + base + (size_t)(qt * 64 + m) * HID + dg);
    }

    float o[4][8];
#pragma unroll
    for (int i = 0; i < 4; ++i)
#pragma unroll
        for (int j = 0; j < 8; ++j) o[i][j] = 0.f;
    float mrow[4] = {-1e30f, -1e30f, -1e30f, -1e30f};
    float lrow[4] = {0.f, 0.f, 0.f, 0.f};

    const float scale = 0.08838834764831845f;   // 1/sqrt(128)

    for (int kt = 0; kt <= qt; ++kt) {
        // load K (transposed) and V tiles
        for (int idx = tid; idx < 64 * 32; idx += 256) {
            const int n  = idx >> 5;
            const int dg = (idx & 31) << 2;
            const size_t roff = base + (size_t)(kt * 64 + n) * HID + dg;
            float4 kv = *(const float4*)(K + roff);
            Kt[(dg + 0) * 64 + n] = kv.x;
            Kt[(dg + 1) * 64 + n] = kv.y;
            Kt[(dg + 2) * 64 + n] = kv.z;
            Kt[(dg + 3) * 64 + n] = kv.w;
            *(float4*)&Vs[n * 128 + dg] = *(const float4*)(V + roff);
        }
        __syncthreads();

        // scores S = Q * K^T  (4x4 per thread)
        float sacc[4][4];
#pragma unroll
        for (int i = 0; i < 4; ++i)
#pragma unroll
            for (int j = 0; j < 4; ++j) sacc[i][j] = 0.f;

        for (int k = 0; k < 128; ++k) {
            const float a0 = Qs[(ty * 4 + 0) * 128 + k];
            const float a1 = Qs[(ty * 4 + 1) * 128 + k];
            const float a2 = Qs[(ty * 4 + 2) * 128 + k];
            const float a3 = Qs[(ty * 4 + 3) * 128 + k];
            const float4 bv = *(const float4*)&Kt[k * 64 + tx * 4];
            sacc[0][0] += a0 * bv.x; sacc[0][1] += a0 * bv.y; sacc[0][2] += a0 * bv.z; sacc[0][3] += a0 * bv.w;
            sacc[1][0] += a1 * bv.x; sacc[1][1] += a1 * bv.y; sacc[1][2] += a1 * bv.z; sacc[1][3] += a1 * bv.w;
            sacc[2][0] += a2 * bv.x; sacc[2][1] += a2 * bv.y; sacc[2][2] += a2 * bv.z; sacc[2][3] += a2 * bv.w;
            sacc[3][0] += a3 * bv.x; sacc[3][1] += a3 * bv.y; sacc[3][2] += a3 * bv.z; sacc[3][3] += a3 * bv.w;
        }

        const bool diag = (kt == qt);
#pragma unroll
        for (int i = 0; i < 4; ++i) {
            float v[4];
#pragma unroll
            for (int j = 0; j < 4; ++j) {
                float val = sacc[i][j] * scale;
                if (diag && (tx * 4 + j) > (ty * 4 + i)) val = -1e30f;
                v[j] = val;
            }
            float lm = fmaxf(fmaxf(v[0], v[1]), fmaxf(v[2], v[3]));
#pragma unroll
            for (int d = 1; d < 16; d <<= 1)
                lm = fmaxf(lm, __shfl_xor_sync(0xffffffffu, lm, d));

            const float mn = fmaxf(mrow[i], lm);
            const float sc = __expf(mrow[i] - mn);
            float ps = 0.f;
#pragma unroll
            for (int j = 0; j < 4; ++j) {
                const float p = __expf(v[j] - mn);
                Ps[(ty * 4 + i) * 64 + tx * 4 + j] = p;
                ps += p;
            }
#pragma unroll
            for (int d = 1; d < 16; d <<= 1)
                ps += __shfl_xor_sync(0xffffffffu, ps, d);

            lrow[i] = lrow[i] * sc + ps;
            mrow[i] = mn;
#pragma unroll
            for (int j = 0; j < 8; ++j) o[i][j] *= sc;
        }
        __syncthreads();

        // O += P * V   (4 rows x 8 cols per thread)
        for (int kk = 0; kk < 64; ++kk) {
            const float a0 = Ps[(ty * 4 + 0) * 64 + kk];
            const float a1 = Ps[(ty * 4 + 1) * 64 + kk];
            const float a2 = Ps[(ty * 4 + 2) * 64 + kk];
            const float a3 = Ps[(ty * 4 + 3) * 64 + kk];
            const float4 b0 = *(const float4*)&Vs[kk * 128 + tx * 8];
            const float4 b1 = *(const float4*)&Vs[kk * 128 + tx * 8 + 4];
            o[0][0] += a0 * b0.x; o[0][1] += a0 * b0.y; o[0][2] += a0 * b0.z; o[0][3] += a0 * b0.w;
            o[0][4] += a0 * b1.x; o[0][5] += a0 * b1.y; o[0][6] += a0 * b1.z; o[0][7] += a0 * b1.w;
            o[1][0] += a1 * b0.x; o[1][1] += a1 * b0.y; o[1][2] += a1 * b0.z; o[1][3] += a1 * b0.w;
            o[1][4] += a1 * b1.x; o[1][5] += a1 * b1.y; o[1][6] += a1 * b1.z; o[1][7] += a1 * b1.w;
            o[2][0] += a2 * b0.x; o[2][1] += a2 * b0.y; o[2][2] += a2 * b0.z; o[2][3] += a2 * b0.w;
            o[2][4] += a2 * b1.x; o[2][5] += a2 * b1.y; o[2][6] += a2 * b1.z; o[2][7] += a2 * b1.w;
            o[3][0] += a3 * b0.x; o[3][1] += a3 * b0.y; o[3][2] += a3 * b0.z; o[3][3] += a3 * b0.w;
            o[3][4] += a3 * b1.x; o[3][5] += a3 * b1.y; o[3][6] += a3 * b1.z; o[3][7] += a3 * b1.w;
        }
        __syncthreads();
    }

    // epilogue: normalize and store
#pragma unroll
    for (int i = 0; i < 4; ++i) {
        const float inv = 1.0f / lrow[i];
        const int row = qt * 64 + ty * 4 + i;
        float4 v0 = make_float4(o[i][0] * inv, o[i][1] * inv, o[i][2] * inv, o[i][3] * inv);
        float4 v1 = make_float4(o[i][4] * inv, o[i][5] * inv, o[i][6] * inv, o[i][7] * inv);
        float* Op = O + base + (size_t)row * HID + tx * 8;
        *(float4*)(Op)     = v0;
        *(float4*)(Op + 4) = v1;
    }
}

// ---------------------------------------------------------------------------
extern "C" void kernel_launch(void* const* d_in, const int* in_sizes, int n_in,
                              void* d_out, int out_size)
{
    const float* X  = (const float*)d_in[0];
    // d_in[1] = attention_mask (causal; implemented analytically, unused)
    const float* Wq = (const float*)d_in[2];
    const float* Wk = (const float*)d_in[3];
    const float* Wv = (const float*)d_in[4];
    const float* Wo = (const float*)d_in[5];
    float* out = (float*)d_out;

    float *Qp, *Kp, *Vp, *Op;
    cudaGetSymbolAddress((void**)&Qp, g_Q);
    cudaGetSymbolAddress((void**)&Kp, g_K);
    cudaGetSymbolAddress((void**)&Vp, g_V);
    cudaGetSymbolAddress((void**)&Op, g_O);

    const int smem_flash = (64 * 128 + 128 * 64 + 64 * 128 + 64 * 64) * 4; // 114688
    cudaFuncSetAttribute(flash_kernel,
                         cudaFuncAttributeMaxDynamicSharedMemorySize, smem_flash);

    dim3 gg(HID / 128, MROWS / 128);   // (16, 32)

    sgemm_nt<<<gg, 256>>>(X, Wq, Qp, MROWS, HID, HID);
    sgemm_nt<<<gg, 256>>>(X, Wk, Kp, MROWS, HID, HID);
    sgemm_nt<<<gg, 256>>>(X, Wv, Vp, MROWS, HID, HID);

    const int rope_total = BSZ * SEQ * NHEAD * 64;
    rope_kernel<<<rope_total / 256, 256>>>(Qp);
    rope_kernel<<<rope_total / 256, 256>>>(Kp);

    flash_kernel<<<dim3(SEQ / 64, NHEAD, BSZ), 256, smem_flash>>>(Qp, Kp, Vp, Op);

    sgemm_nt<<<gg, 256>>>(Op, Wo, out, MROWS, HID, HID);
}

// round 3
// speedup vs baseline: 1.6857x; 1.6857x over previous
#include <cuda_runtime.h>
#include <cstdint>

#define BSZ   2
#define SEQ   2048
#define HID   2048
#define NHEAD 16
#define HDIM  128
#define MROWS (BSZ*SEQ)     // 4096
#define GK    2048
#define GN    2048

// ---------------- scratch (static device arrays; no allocation) -------------
__device__ float g_Q[(size_t)MROWS * HID];
__device__ float g_K[(size_t)MROWS * HID];
__device__ float g_V[(size_t)MROWS * HID];
__device__ float g_O[(size_t)MROWS * HID];

// ---------------------------------------------------------------------------
__device__ __forceinline__ uint32_t f2tf32(float x) {
    uint32_t r;
    asm("cvt.rna.tf32.f32 %0, %1;" : "=r"(r) : "f"(x));
    return r;
}

__device__ __forceinline__ void mma_tf32_16x8x8(float c[4],
                                                uint32_t a0, uint32_t a1,
                                                uint32_t a2, uint32_t a3,
                                                uint32_t b0, uint32_t b1)
{
    asm volatile(
        "mma.sync.aligned.m16n8k8.row.col.f32.tf32.tf32.f32 "
        "{%0,%1,%2,%3}, {%4,%5,%6,%7}, {%8,%9}, {%0,%1,%2,%3};"
        : "+f"(c[0]), "+f"(c[1]), "+f"(c[2]), "+f"(c[3])
        : "r"(a0), "r"(a1), "r"(a2), "r"(a3), "r"(b0), "r"(b1));
}

// ---------------------------------------------------------------------------
// tf32 mma.sync GEMM:  C[M,N] = A[M,K] * B[N,K]^T   (row-major, K contiguous)
// CTA tile 128x128, BK=16, double-buffered smem, 256 threads.
// 8 warps as 4(m) x 2(n); warp tile 32x64 = 2 m-tiles x 8 n-tiles of 16x8.
// Smem rows padded to 20 floats -> conflict-free fragment loads.
// ---------------------------------------------------------------------------
__global__ void __launch_bounds__(256) gemm_tf32(const float* __restrict__ A,
                                                 const float* __restrict__ B,
                                                 float* __restrict__ C)
{
    __shared__ float As[2][128][20];
    __shared__ float Bs[2][128][20];

    const int tid = threadIdx.x;
    const int wid = tid >> 5;
    const int lid = tid & 31;
    const int g   = lid >> 2;      // group id 0..7
    const int tg  = lid & 3;       // thread-in-group 0..3
    const int mbase = (wid & 3) * 32;
    const int nbase = (wid >> 2) * 64;
    const int bm = blockIdx.y * 128;
    const int bn = blockIdx.x * 128;

    const float* Ap = A + (size_t)bm * GK;
    const float* Bp = B + (size_t)bn * GK;

    // per-thread load coords: 2 float4 per matrix per buffer
    const int lm0 = tid >> 1;                 // rows 0..127 (pair 0)
    const int lk0 = (tid & 1) << 3;           // k offset 0 or 8
    // pattern: idx = l*256 + tid ; m = idx>>2 ; kg = (idx&3)*4
    float c[2][8][4];
#pragma unroll
    for (int i = 0; i < 2; ++i)
#pragma unroll
        for (int j = 0; j < 8; ++j)
#pragma unroll
            for (int q = 0; q < 4; ++q) c[i][j][q] = 0.f;

    float4 ra[2], rb[2];

    // ---- prologue: load k-chunk 0 into buffer 0
#pragma unroll
    for (int l = 0; l < 2; ++l) {
        const int idx = l * 256 + tid;
        const int m   = idx >> 2;
        const int kg  = (idx & 3) << 2;
        ra[l] = *(const float4*)(Ap + (size_t)m * GK + kg);
        rb[l] = *(const float4*)(Bp + (size_t)m * GK + kg);
    }
#pragma unroll
    for (int l = 0; l < 2; ++l) {
        const int idx = l * 256 + tid;
        const int m   = idx >> 2;
        const int kg  = (idx & 3) << 2;
        As[0][m][kg + 0] = __uint_as_float(f2tf32(ra[l].x));
        As[0][m][kg + 1] = __uint_as_float(f2tf32(ra[l].y));
        As[0][m][kg + 2] = __uint_as_float(f2tf32(ra[l].z));
        As[0][m][kg + 3] = __uint_as_float(f2tf32(ra[l].w));
        Bs[0][m][kg + 0] = __uint_as_float(f2tf32(rb[l].x));
        Bs[0][m][kg + 1] = __uint_as_float(f2tf32(rb[l].y));
        Bs[0][m][kg + 2] = __uint_as_float(f2tf32(rb[l].z));
        Bs[0][m][kg + 3] = __uint_as_float(f2tf32(rb[l].w));
    }
    __syncthreads();

    const int NIT = GK / 16;   // 128
    for (int it = 0; it < NIT; ++it) {
        const int p = it & 1;

        if (it + 1 < NIT) {
            const int k0 = (it + 1) * 16;
#pragma unroll
            for (int l = 0; l < 2; ++l) {
                const int idx = l * 256 + tid;
                const int m   = idx >> 2;
                const int kg  = (idx & 3) << 2;
                ra[l] = *(const float4*)(Ap + (size_t)m * GK + k0 + kg);
                rb[l] = *(const float4*)(Bp + (size_t)m * GK + k0 + kg);
            }
        }

        // ---- compute: two k8 steps over buffer p
#pragma unroll
        for (int ks = 0; ks < 2; ++ks) {
            const int kk = ks * 8;
            uint32_t af[2][4], bf[8][2];
#pragma unroll
            for (int mt = 0; mt < 2; ++mt) {
                const int r0 = mbase + mt * 16 + g;
                af[mt][0] = __float_as_uint(As[p][r0][kk + tg]);
                af[mt][1] = __float_as_uint(As[p][r0 + 8][kk + tg]);
                af[mt][2] = __float_as_uint(As[p][r0][kk + tg + 4]);
                af[mt][3] = __float_as_uint(As[p][r0 + 8][kk + tg + 4]);
            }
#pragma unroll
            for (int nt = 0; nt < 8; ++nt) {
                const int n0 = nbase + nt * 8 + g;
                bf[nt][0] = __float_as_uint(Bs[p][n0][kk + tg]);
                bf[nt][1] = __float_as_uint(Bs[p][n0][kk + tg + 4]);
            }
#pragma unroll
            for (int mt = 0; mt < 2; ++mt)
#pragma unroll
                for (int nt = 0; nt < 8; ++nt)
                    mma_tf32_16x8x8(c[mt][nt], af[mt][0], af[mt][1], af[mt][2], af[mt][3],
                                    bf[nt][0], bf[nt][1]);
        }

        if (it + 1 < NIT) {
            const int pn = p ^ 1;
#pragma unroll
            for (int l = 0; l < 2; ++l) {
                const int idx = l * 256 + tid;
                const int m   = idx >> 2;
                const int kg  = (idx & 3) << 2;
                As[pn][m][kg + 0] = __uint_as_float(f2tf32(ra[l].x));
                As[pn][m][kg + 1] = __uint_as_float(f2tf32(ra[l].y));
                As[pn][m][kg + 2] = __uint_as_float(f2tf32(ra[l].z));
                As[pn][m][kg + 3] = __uint_as_float(f2tf32(ra[l].w));
                Bs[pn][m][kg + 0] = __uint_as_float(f2tf32(rb[l].x));
                Bs[pn][m][kg + 1] = __uint_as_float(f2tf32(rb[l].y));
                Bs[pn][m][kg + 2] = __uint_as_float(f2tf32(rb[l].z));
                Bs[pn][m][kg + 3] = __uint_as_float(f2tf32(rb[l].w));
            }
            __syncthreads();
        }
    }

    // ---- epilogue
#pragma unroll
    for (int mt = 0; mt < 2; ++mt) {
        const int r0 = bm + mbase + mt * 16 + g;
#pragma unroll
        for (int nt = 0; nt < 8; ++nt) {
            const int cc = bn + nbase + nt * 8 + 2 * tg;
            *(float2*)(C + (size_t)r0 * GN + cc)       = make_float2(c[mt][nt][0], c[mt][nt][1]);
            *(float2*)(C + (size_t)(r0 + 8) * GN + cc) = make_float2(c[mt][nt][2], c[mt][nt][3]);
        }
    }
}

// ---------------------------------------------------------------------------
// RoPE in place on [B,S,H] with per-head dim 128 (half = 64).
// ---------------------------------------------------------------------------
__global__ void __launch_bounds__(256) rope_kernel(float* __restrict__ X)
{
    const int i  = blockIdx.x * blockDim.x + threadIdx.x;
    const int j  = i & 63;
    const int t  = i >> 6;
    const int h  = t & (NHEAD - 1);
    const int t2 = t >> 4;
    const int s  = t2 & (SEQ - 1);
    const int b  = t2 >> 11;

    float* p = X + ((size_t)(b * SEQ + s)) * HID + h * HDIM;

    const float invf = powf(10000.0f, -(float)j * (1.0f / 64.0f));
    const float ang  = (float)s * invf;
    float sn, cs;
    sincosf(ang, &sn, &cs);

    const float x1 = p[j];
    const float x2 = p[j + 64];
    p[j]      = x1 * cs - x2 * sn;
    p[j + 64] = x2 * cs + x1 * sn;
}

// ---------------------------------------------------------------------------
// Flash attention (fp32, causal). Block = 256 threads handles one 64-row
// Q tile of one (b,h). Iterates K/V tiles 0..qt with online softmax.
// ---------------------------------------------------------------------------
__global__ void __launch_bounds__(256) flash_kernel(const float* __restrict__ Q,
                                                    const float* __restrict__ K,
                                                    const float* __restrict__ V,
                                                    float* __restrict__ O)
{
    extern __shared__ float smf[];
    float* Qs = smf;              // 64*128
    float* Kt = Qs + 64 * 128;    // 128*64
    float* Vs = Kt + 128 * 64;    // 64*128
    float* Ps = Vs + 64 * 128;    // 64*64

    const int tid = threadIdx.x;
    const int tx  = tid & 15;
    const int ty  = tid >> 4;
    const int qt  = blockIdx.x;
    const int h   = blockIdx.y;
    const int b   = blockIdx.z;

    const size_t base = ((size_t)b * SEQ) * HID + (size_t)h * HDIM;

    for (int idx = tid; idx < 64 * 32; idx += 256) {
        const int m  = idx >> 5;
        const int dg = (idx & 31) << 2;
        *(float4*)&Qs[m * 128 + dg] =
            *(const float4*)(Q + base + (size_t)(qt * 64 + m) * HID + dg);
    }

    float o[4][8];
#pragma unroll
    for (int i = 0; i < 4; ++i)
#pragma unroll
        for (int j = 0; j < 8; ++j) o[i][j] = 0.f;
    float mrow[4] = {-1e30f, -1e30f, -1e30f, -1e30f};
    float lrow[4] = {0.f, 0.f, 0.f, 0.f};

    const float scale = 0.08838834764831845f;   // 1/sqrt(128)

    for (int kt = 0; kt <= qt; ++kt) {
        for (int idx = tid; idx < 64 * 32; idx += 256) {
            const int n  = idx >> 5;
            const int dg = (idx & 31) << 2;
            const size_t roff = base + (size_t)(kt * 64 + n) * HID + dg;
            float4 kv = *(const float4*)(K + roff);
            Kt[(dg + 0) * 64 + n] = kv.x;
            Kt[(dg + 1) * 64 + n] = kv.y;
            Kt[(dg + 2) * 64 + n] = kv.z;
            Kt[(dg + 3) * 64 + n] = kv.w;
            *(float4*)&Vs[n * 128 + dg] = *(const float4*)(V + roff);
        }
        __syncthreads();

        float sacc[4][4];
#pragma unroll
        for (int i = 0; i < 4; ++i)
#pragma unroll
            for (int j = 0; j < 4; ++j) sacc[i][j] = 0.f;

        for (int k = 0; k < 128; ++k) {
            const float a0 = Qs[(ty * 4 + 0) * 128 + k];
            const float a1 = Qs[(ty * 4 + 1) * 128 + k];
            const float a2 = Qs[(ty * 4 + 2) * 128 + k];
            const float a3 = Qs[(ty * 4 + 3) * 128 + k];
            const float4 bv = *(const float4*)&Kt[k * 64 + tx * 4];
            sacc[0][0] += a0 * bv.x; sacc[0][1] += a0 * bv.y; sacc[0][2] += a0 * bv.z; sacc[0][3] += a0 * bv.w;
            sacc[1][0] += a1 * bv.x; sacc[1][1] += a1 * bv.y; sacc[1][2] += a1 * bv.z; sacc[1][3] += a1 * bv.w;
            sacc[2][0] += a2 * bv.x; sacc[2][1] += a2 * bv.y; sacc[2][2] += a2 * bv.z; sacc[2][3] += a2 * bv.w;
            sacc[3][0] += a3 * bv.x; sacc[3][1] += a3 * bv.y; sacc[3][2] += a3 * bv.z; sacc[3][3] += a3 * bv.w;
        }

        const bool diag = (kt == qt);
#pragma unroll
        for (int i = 0; i < 4; ++i) {
            float v[4];
#pragma unroll
            for (int j = 0; j < 4; ++j) {
                float val = sacc[i][j] * scale;
                if (diag && (tx * 4 + j) > (ty * 4 + i)) val = -1e30f;
                v[j] = val;
            }
            float lm = fmaxf(fmaxf(v[0], v[1]), fmaxf(v[2], v[3]));
#pragma unroll
            for (int d = 1; d < 16; d <<= 1)
                lm = fmaxf(lm, __shfl_xor_sync(0xffffffffu, lm, d));

            const float mn = fmaxf(mrow[i], lm);
            const float sc = __expf(mrow[i] - mn);
            float ps = 0.f;
#pragma unroll
            for (int j = 0; j < 4; ++j) {
                const float p = __expf(v[j] - mn);
                Ps[(ty * 4 + i) * 64 + tx * 4 + j] = p;
                ps += p;
            }
#pragma unroll
            for (int d = 1; d < 16; d <<= 1)
                ps += __shfl_xor_sync(0xffffffffu, ps, d);

            lrow[i] = lrow[i] * sc + ps;
            mrow[i] = mn;
#pragma unroll
            for (int j = 0; j < 8; ++j) o[i][j] *= sc;
        }
        __syncthreads();

        for (int kk = 0; kk < 64; ++kk) {
            const float a0 = Ps[(ty * 4 + 0) * 64 + kk];
            const float a1 = Ps[(ty * 4 + 1) * 64 + kk];
            const float a2 = Ps[(ty * 4 + 2) * 64 + kk];
            const float a3 = Ps[(ty * 4 + 3) * 64 + kk];
            const float4 b0 = *(const float4*)&Vs[kk * 128 + tx * 8];
            const float4 b1 = *(const float4*)&Vs[kk * 128 + tx * 8 + 4];
            o[0][0] += a0 * b0.x; o[0][1] += a0 * b0.y; o[0][2] += a0 * b0.z; o[0][3] += a0 * b0.w;
            o[0][4] += a0 * b1.x; o[0][5] += a0 * b1.y; o[0][6] += a0 * b1.z; o[0][7] += a0 * b1.w;
            o[1][0] += a1 * b0.x; o[1][1] += a1 * b0.y; o[1][2] += a1 * b0.z; o[1][3] += a1 * b0.w;
            o[1][4] += a1 * b1.x; o[1][5] += a1 * b1.y; o[1][6] += a1 * b1.z; o[1][7] += a1 * b1.w;
            o[2][0] += a2 * b0.x; o[2][1] += a2 * b0.y; o[2][2] += a2 * b0.z; o[2][3] += a2 * b0.w;
            o[2][4] += a2 * b1.x; o[2][5] += a2 * b1.y; o[2][6] += a2 * b1.z; o[2][7] += a2 * b1.w;
            o[3][0] += a3 * b0.x; o[3][1] += a3 * b0.y; o[3][2] += a3 * b0.z; o[3][3] += a3 * b0.w;
            o[3][4] += a3 * b1.x; o[3][5] += a3 * b1.y; o[3][6] += a3 * b1.z; o[3][7] += a3 * b1.w;
        }
        __syncthreads();
    }

#pragma unroll
    for (int i = 0; i < 4; ++i) {
        const float inv = 1.0f / lrow[i];
        const int row = qt * 64 + ty * 4 + i;
        float4 v0 = make_float4(o[i][0] * inv, o[i][1] * inv, o[i][2] * inv, o[i][3] * inv);
        float4 v1 = make_float4(o[i][4] * inv, o[i][5] * inv, o[i][6] * inv, o[i][7] * inv);
        float* Op = O + base + (size_t)row * HID + tx * 8;
        *(float4*)(Op)     = v0;
        *(float4*)(Op + 4) = v1;
    }
}

// ---------------------------------------------------------------------------
extern "C" void kernel_launch(void* const* d_in, const int* in_sizes, int n_in,
                              void* d_out, int out_size)
{
    const float* X  = (const float*)d_in[0];
    // d_in[1] = attention_mask (causal; implemented analytically, unused)
    const float* Wq = (const float*)d_in[2];
    const float* Wk = (const float*)d_in[3];
    const float* Wv = (const float*)d_in[4];
    const float* Wo = (const float*)d_in[5];
    float* out = (float*)d_out;

    float *Qp, *Kp, *Vp, *Op;
    cudaGetSymbolAddress((void**)&Qp, g_Q);
    cudaGetSymbolAddress((void**)&Kp, g_K);
    cudaGetSymbolAddress((void**)&Vp, g_V);
    cudaGetSymbolAddress((void**)&Op, g_O);

    const int smem_flash = (64 * 128 + 128 * 64 + 64 * 128 + 64 * 64) * 4; // 114688
    cudaFuncSetAttribute(flash_kernel,
                         cudaFuncAttributeMaxDynamicSharedMemorySize, smem_flash);

    dim3 gg(GN / 128, MROWS / 128);   // (16, 32)

    gemm_tf32<<<gg, 256>>>(X, Wq, Qp);
    gemm_tf32<<<gg, 256>>>(X, Wk, Kp);
    gemm_tf32<<<gg, 256>>>(X, Wv, Vp);

    const int rope_total = BSZ * SEQ * NHEAD * 64;
    rope_kernel<<<rope_total / 256, 256>>>(Qp);
    rope_kernel<<<rope_total / 256, 256>>>(Kp);

    flash_kernel<<<dim3(SEQ / 64, NHEAD, BSZ), 256, smem_flash>>>(Qp, Kp, Vp, Op);

    gemm_tf32<<<gg, 256>>>(Op, Wo, out);
}

// round 4
// speedup vs baseline: 2.9677x; 1.7605x over previous
#include <cuda_runtime.h>
#include <cstdint>

#define BSZ   2
#define SEQ   2048
#define HID   2048
#define NHEAD 16
#define HDIM  128
#define MROWS (BSZ*SEQ)     // 4096
#define GK    2048
#define GN    2048

// ---------------- scratch (static device arrays; no allocation) -------------
__device__ float g_Q[(size_t)MROWS * HID];
__device__ float g_K[(size_t)MROWS * HID];
__device__ float g_V[(size_t)MROWS * HID];
__device__ float g_O[(size_t)MROWS * HID];

// ---------------------------------------------------------------------------
__device__ __forceinline__ uint32_t f2tf32(float x) {
    uint32_t r;
    asm("cvt.rna.tf32.f32 %0, %1;" : "=r"(r) : "f"(x));
    return r;
}
__device__ __forceinline__ float tf32f(float x) {
    return __uint_as_float(f2tf32(x));
}

__device__ __forceinline__ void mma_tf32_16x8x8(float c[4],
                                                uint32_t a0, uint32_t a1,
                                                uint32_t a2, uint32_t a3,
                                                uint32_t b0, uint32_t b1)
{
    asm volatile(
        "mma.sync.aligned.m16n8k8.row.col.f32.tf32.tf32.f32 "
        "{%0,%1,%2,%3}, {%4,%5,%6,%7}, {%8,%9}, {%0,%1,%2,%3};"
        : "+f"(c[0]), "+f"(c[1]), "+f"(c[2]), "+f"(c[3])
        : "r"(a0), "r"(a1), "r"(a2), "r"(a3), "r"(b0), "r"(b1));
}

// ---------------------------------------------------------------------------
// tf32 mma.sync GEMM:  C[M,N] = A[M,K] * B[N,K]^T   (unchanged from R3)
// ---------------------------------------------------------------------------
__global__ void __launch_bounds__(256) gemm_tf32(const float* __restrict__ A,
                                                 const float* __restrict__ B,
                                                 float* __restrict__ C)
{
    __shared__ float As[2][128][20];
    __shared__ float Bs[2][128][20];

    const int tid = threadIdx.x;
    const int wid = tid >> 5;
    const int lid = tid & 31;
    const int g   = lid >> 2;
    const int tg  = lid & 3;
    const int mbase = (wid & 3) * 32;
    const int nbase = (wid >> 2) * 64;
    const int bm = blockIdx.y * 128;
    const int bn = blockIdx.x * 128;

    const float* Ap = A + (size_t)bm * GK;
    const float* Bp = B + (size_t)bn * GK;

    float c[2][8][4];
#pragma unroll
    for (int i = 0; i < 2; ++i)
#pragma unroll
        for (int j = 0; j < 8; ++j)
#pragma unroll
            for (int q = 0; q < 4; ++q) c[i][j][q] = 0.f;

    float4 ra[2], rb[2];

#pragma unroll
    for (int l = 0; l < 2; ++l) {
        const int idx = l * 256 + tid;
        const int m   = idx >> 2;
        const int kg  = (idx & 3) << 2;
        ra[l] = *(const float4*)(Ap + (size_t)m * GK + kg);
        rb[l] = *(const float4*)(Bp + (size_t)m * GK + kg);
    }
#pragma unroll
    for (int l = 0; l < 2; ++l) {
        const int idx = l * 256 + tid;
        const int m   = idx >> 2;
        const int kg  = (idx & 3) << 2;
        As[0][m][kg + 0] = tf32f(ra[l].x);
        As[0][m][kg + 1] = tf32f(ra[l].y);
        As[0][m][kg + 2] = tf32f(ra[l].z);
        As[0][m][kg + 3] = tf32f(ra[l].w);
        Bs[0][m][kg + 0] = tf32f(rb[l].x);
        Bs[0][m][kg + 1] = tf32f(rb[l].y);
        Bs[0][m][kg + 2] = tf32f(rb[l].z);
        Bs[0][m][kg + 3] = tf32f(rb[l].w);
    }
    __syncthreads();

    const int NIT = GK / 16;   // 128
    for (int it = 0; it < NIT; ++it) {
        const int p = it & 1;

        if (it + 1 < NIT) {
            const int k0 = (it + 1) * 16;
#pragma unroll
            for (int l = 0; l < 2; ++l) {
                const int idx = l * 256 + tid;
                const int m   = idx >> 2;
                const int kg  = (idx & 3) << 2;
                ra[l] = *(const float4*)(Ap + (size_t)m * GK + k0 + kg);
                rb[l] = *(const float4*)(Bp + (size_t)m * GK + k0 + kg);
            }
        }

#pragma unroll
        for (int ks = 0; ks < 2; ++ks) {
            const int kk = ks * 8;
            uint32_t af[2][4], bf[8][2];
#pragma unroll
            for (int mt = 0; mt < 2; ++mt) {
                const int r0 = mbase + mt * 16 + g;
                af[mt][0] = __float_as_uint(As[p][r0][kk + tg]);
                af[mt][1] = __float_as_uint(As[p][r0 + 8][kk + tg]);
                af[mt][2] = __float_as_uint(As[p][r0][kk + tg + 4]);
                af[mt][3] = __float_as_uint(As[p][r0 + 8][kk + tg + 4]);
            }
#pragma unroll
            for (int nt = 0; nt < 8; ++nt) {
                const int n0 = nbase + nt * 8 + g;
                bf[nt][0] = __float_as_uint(Bs[p][n0][kk + tg]);
                bf[nt][1] = __float_as_uint(Bs[p][n0][kk + tg + 4]);
            }
#pragma unroll
            for (int mt = 0; mt < 2; ++mt)
#pragma unroll
                for (int nt = 0; nt < 8; ++nt)
                    mma_tf32_16x8x8(c[mt][nt], af[mt][0], af[mt][1], af[mt][2], af[mt][3],
                                    bf[nt][0], bf[nt][1]);
        }

        if (it + 1 < NIT) {
            const int pn = p ^ 1;
#pragma unroll
            for (int l = 0; l < 2; ++l) {
                const int idx = l * 256 + tid;
                const int m   = idx >> 2;
                const int kg  = (idx & 3) << 2;
                As[pn][m][kg + 0] = tf32f(ra[l].x);
                As[pn][m][kg + 1] = tf32f(ra[l].y);
                As[pn][m][kg + 2] = tf32f(ra[l].z);
                As[pn][m][kg + 3] = tf32f(ra[l].w);
                Bs[pn][m][kg + 0] = tf32f(rb[l].x);
                Bs[pn][m][kg + 1] = tf32f(rb[l].y);
                Bs[pn][m][kg + 2] = tf32f(rb[l].z);
                Bs[pn][m][kg + 3] = tf32f(rb[l].w);
            }
            __syncthreads();
        }
    }

#pragma unroll
    for (int mt = 0; mt < 2; ++mt) {
        const int r0 = bm + mbase + mt * 16 + g;
#pragma unroll
        for (int nt = 0; nt < 8; ++nt) {
            const int cc = bn + nbase + nt * 8 + 2 * tg;
            *(float2*)(C + (size_t)r0 * GN + cc)       = make_float2(c[mt][nt][0], c[mt][nt][1]);
            *(float2*)(C + (size_t)(r0 + 8) * GN + cc) = make_float2(c[mt][nt][2], c[mt][nt][3]);
        }
    }
}

// ---------------------------------------------------------------------------
// RoPE in place on [B,S,H] with per-head dim 128 (half = 64).
// ---------------------------------------------------------------------------
__global__ void __launch_bounds__(256) rope_kernel(float* __restrict__ X)
{
    const int i  = blockIdx.x * blockDim.x + threadIdx.x;
    const int j  = i & 63;
    const int t  = i >> 6;
    const int h  = t & (NHEAD - 1);
    const int t2 = t >> 4;
    const int s  = t2 & (SEQ - 1);
    const int b  = t2 >> 11;

    float* p = X + ((size_t)(b * SEQ + s)) * HID + h * HDIM;

    const float invf = powf(10000.0f, -(float)j * (1.0f / 64.0f));
    const float ang  = (float)s * invf;
    float sn, cs;
    sincosf(ang, &sn, &cs);

    const float x1 = p[j];
    const float x2 = p[j + 64];
    p[j]      = x1 * cs - x2 * sn;
    p[j + 64] = x2 * cs + x1 * sn;
}

// ---------------------------------------------------------------------------
// Flash attention on tensor cores (tf32 mma.sync, causal, online softmax).
// CTA: 128 q-rows of one (b,h); 8 warps x 16 rows. KV tile = 64.
// smem: Qs[128][132] tf32, Ks[64][132] tf32, Vt[128][68] (V^T, tf32),
//       Ps[128][68] (P tf32).
// ---------------------------------------------------------------------------
#define PQK 132
#define PV  68

__global__ void __launch_bounds__(256) flash_mma(const float* __restrict__ Q,
                                                 const float* __restrict__ K,
                                                 const float* __restrict__ V,
                                                 float* __restrict__ O)
{
    extern __shared__ float smf[];
    float* Qs = smf;                    // 128*132
    float* Ks = Qs + 128 * PQK;         // 64*132
    float* Vt = Ks + 64 * PQK;          // 128*68
    float* Ps = Vt + 128 * PV;          // 128*68

    const int tid = threadIdx.x;
    const int wid = tid >> 5;
    const int lid = tid & 31;
    const int g   = lid >> 2;
    const int tg  = lid & 3;
    const int r0  = wid * 16;
    const int q0  = blockIdx.x * 128;
    const size_t base = ((size_t)blockIdx.z * SEQ) * HID + (size_t)blockIdx.y * HDIM;

    // ---- load Q tile (tf32)
    for (int idx = tid; idx < 128 * 32; idx += 256) {
        const int m  = idx >> 5;
        const int dg = (idx & 31) << 2;
        float4 v = *(const float4*)(Q + base + (size_t)(q0 + m) * HID + dg);
        float* dst = &Qs[m * PQK + dg];
        dst[0] = tf32f(v.x); dst[1] = tf32f(v.y);
        dst[2] = tf32f(v.z); dst[3] = tf32f(v.w);
    }
    __syncthreads();

    float o[16][4];
#pragma unroll
    for (int i = 0; i < 16; ++i)
#pragma unroll
        for (int j = 0; j < 4; ++j) o[i][j] = 0.f;
    float mrow[2] = {-1e30f, -1e30f};
    float lrow[2] = {0.f, 0.f};

    const float scale = 0.08838834764831845f;   // 1/sqrt(128)
    const int nkv = q0 / 64 + 2;

    for (int kt = 0; kt < nkv; ++kt) {
        const int kv0 = kt * 64;

        // ---- load K tile (row layout, tf32)
        for (int idx = tid; idx < 64 * 32; idx += 256) {
            const int n  = idx >> 5;
            const int dg = (idx & 31) << 2;
            float4 kv = *(const float4*)(K + base + (size_t)(kv0 + n) * HID + dg);
            float* dst = &Ks[n * PQK + dg];
            dst[0] = tf32f(kv.x); dst[1] = tf32f(kv.y);
            dst[2] = tf32f(kv.z); dst[3] = tf32f(kv.w);
        }
        // ---- load V tile transposed (Vt[d][kv], tf32)
#pragma unroll
        for (int l = 0; l < 8; ++l) {
            const int tile = l * 8 + wid;
            const int n = (tile & 7) * 8 + (lid >> 2);
            const int d = (tile >> 3) * 16 + (lid & 3) * 4;
            float4 vv = *(const float4*)(V + base + (size_t)(kv0 + n) * HID + d);
            Vt[(d + 0) * PV + n] = tf32f(vv.x);
            Vt[(d + 1) * PV + n] = tf32f(vv.y);
            Vt[(d + 2) * PV + n] = tf32f(vv.z);
            Vt[(d + 3) * PV + n] = tf32f(vv.w);
        }
        __syncthreads();

        // ---- S = Q K^T  (warp rows r0..r0+15, cols 0..63)
        float s[8][4];
#pragma unroll
        for (int nt = 0; nt < 8; ++nt)
#pragma unroll
            for (int j = 0; j < 4; ++j) s[nt][j] = 0.f;

#pragma unroll
        for (int ks = 0; ks < 16; ++ks) {
            const int kk = ks * 8;
            const uint32_t a0 = __float_as_uint(Qs[(r0 + g) * PQK + kk + tg]);
            const uint32_t a1 = __float_as_uint(Qs[(r0 + g + 8) * PQK + kk + tg]);
            const uint32_t a2 = __float_as_uint(Qs[(r0 + g) * PQK + kk + tg + 4]);
            const uint32_t a3 = __float_as_uint(Qs[(r0 + g + 8) * PQK + kk + tg + 4]);
#pragma unroll
            for (int nt = 0; nt < 8; ++nt) {
                const uint32_t b0 = __float_as_uint(Ks[(nt * 8 + g) * PQK + kk + tg]);
                const uint32_t b1 = __float_as_uint(Ks[(nt * 8 + g) * PQK + kk + tg + 4]);
                mma_tf32_16x8x8(s[nt], a0, a1, a2, a3, b0, b1);
            }
        }

        // ---- online softmax on fragments
        const bool needm = (kv0 + 63 > q0 + r0);
#pragma unroll
        for (int i = 0; i < 2; ++i) {
            const int rg = q0 + r0 + g + 8 * i;
            float v2[8][2];
            float lm = -1e30f;
#pragma unroll
            for (int nt = 0; nt < 8; ++nt) {
                float va = s[nt][2 * i] * scale;
                float vb = s[nt][2 * i + 1] * scale;
                if (needm) {
                    const int c0 = kv0 + nt * 8 + 2 * tg;
                    if (c0 > rg)     va = -1e30f;
                    if (c0 + 1 > rg) vb = -1e30f;
                }
                v2[nt][0] = va; v2[nt][1] = vb;
                lm = fmaxf(lm, fmaxf(va, vb));
            }
            lm = fmaxf(lm, __shfl_xor_sync(0xffffffffu, lm, 1));
            lm = fmaxf(lm, __shfl_xor_sync(0xffffffffu, lm, 2));

            const float mn = fmaxf(mrow[i], lm);
            const float sc = __expf(mrow[i] - mn);
            float ps = 0.f;
#pragma unroll
            for (int nt = 0; nt < 8; ++nt) {
                float p0 = tf32f(__expf(v2[nt][0] - mn));
                float p1 = tf32f(__expf(v2[nt][1] - mn));
                *(float2*)&Ps[(r0 + g + 8 * i) * PV + nt * 8 + 2 * tg] = make_float2(p0, p1);
                ps += p0 + p1;
            }
            ps += __shfl_xor_sync(0xffffffffu, ps, 1);
            ps += __shfl_xor_sync(0xffffffffu, ps, 2);

            lrow[i] = lrow[i] * sc + ps;
            mrow[i] = mn;
#pragma unroll
            for (int nt = 0; nt < 16; ++nt) {
                o[nt][2 * i]     *= sc;
                o[nt][2 * i + 1] *= sc;
            }
        }
        __syncthreads();

        // ---- O += P V   (A = Ps rows r0..r0+15 x k64, B = Vt d x kv)
#pragma unroll
        for (int ks = 0; ks < 8; ++ks) {
            const int kk = ks * 8;
            const uint32_t a0 = __float_as_uint(Ps[(r0 + g) * PV + kk + tg]);
            const uint32_t a1 = __float_as_uint(Ps[(r0 + g + 8) * PV + kk + tg]);
            const uint32_t a2 = __float_as_uint(Ps[(r0 + g) * PV + kk + tg + 4]);
            const uint32_t a3 = __float_as_uint(Ps[(r0 + g + 8) * PV + kk + tg + 4]);
#pragma unroll
            for (int nt = 0; nt < 16; ++nt) {
                const uint32_t b0 = __float_as_uint(Vt[(nt * 8 + g) * PV + kk + tg]);
                const uint32_t b1 = __float_as_uint(Vt[(nt * 8 + g) * PV + kk + tg + 4]);
                mma_tf32_16x8x8(o[nt], a0, a1, a2, a3, b0, b1);
            }
        }
        __syncthreads();
    }

    // ---- epilogue: normalize, store
    const float inv0 = 1.0f / lrow[0];
    const float inv1 = 1.0f / lrow[1];
#pragma unroll
    for (int nt = 0; nt < 16; ++nt) {
        const int col = nt * 8 + 2 * tg;
        *(float2*)(O + base + (size_t)(q0 + r0 + g) * HID + col) =
            make_float2(o[nt][0] * inv0, o[nt][1] * inv0);
        *(float2*)(O + base + (size_t)(q0 + r0 + g + 8) * HID + col) =
            make_float2(o[nt][2] * inv1, o[nt][3] * inv1);
    }
}

// ---------------------------------------------------------------------------
extern "C" void kernel_launch(void* const* d_in, const int* in_sizes, int n_in,
                              void* d_out, int out_size)
{
    const float* X  = (const float*)d_in[0];
    // d_in[1] = attention_mask (causal; implemented analytically, unused)
    const float* Wq = (const float*)d_in[2];
    const float* Wk = (const float*)d_in[3];
    const float* Wv = (const float*)d_in[4];
    const float* Wo = (const float*)d_in[5];
    float* out = (float*)d_out;

    float *Qp, *Kp, *Vp, *Op;
    cudaGetSymbolAddress((void**)&Qp, g_Q);
    cudaGetSymbolAddress((void**)&Kp, g_K);
    cudaGetSymbolAddress((void**)&Vp, g_V);
    cudaGetSymbolAddress((void**)&Op, g_O);

    const int smem_flash = (128 * PQK + 64 * PQK + 128 * PV + 128 * PV) * 4; // 171008
    cudaFuncSetAttribute(flash_mma,
                         cudaFuncAttributeMaxDynamicSharedMemorySize, smem_flash);

    dim3 gg(GN / 128, MROWS / 128);   // (16, 32)

    gemm_tf32<<<gg, 256>>>(X, Wq, Qp);
    gemm_tf32<<<gg, 256>>>(X, Wk, Kp);
    gemm_tf32<<<gg, 256>>>(X, Wv, Vp);

    const int rope_total = BSZ * SEQ * NHEAD * 64;
    rope_kernel<<<rope_total / 256, 256>>>(Qp);
    rope_kernel<<<rope_total / 256, 256>>>(Kp);

    flash_mma<<<dim3(SEQ / 128, NHEAD, BSZ), 256, smem_flash>>>(Qp, Kp, Vp, Op);

    gemm_tf32<<<gg, 256>>>(Op, Wo, out);
}

// round 5
// speedup vs baseline: 3.3522x; 1.1296x over previous
#include <cuda_runtime.h>
#include <cstdint>

#define BSZ   2
#define SEQ   2048
#define HID   2048
#define NHEAD 16
#define HDIM  128
#define MROWS (BSZ*SEQ)     // 4096
#define GK    2048
#define GN    2048

// ---------------- scratch (static device arrays; no allocation) -------------
__device__ float g_Q[(size_t)MROWS * HID];
__device__ float g_K[(size_t)MROWS * HID];
__device__ float g_V[(size_t)MROWS * HID];
__device__ float g_O[(size_t)MROWS * HID];

// ---------------------------------------------------------------------------
__device__ __forceinline__ uint32_t f2tf32(float x) {
    uint32_t r;
    asm("cvt.rna.tf32.f32 %0, %1;" : "=r"(r) : "f"(x));
    return r;
}
__device__ __forceinline__ float tf32f(float x) {
    return __uint_as_float(f2tf32(x));
}

__device__ __forceinline__ void mma_tf32_16x8x8(float c[4],
                                                uint32_t a0, uint32_t a1,
                                                uint32_t a2, uint32_t a3,
                                                uint32_t b0, uint32_t b1)
{
    asm volatile(
        "mma.sync.aligned.m16n8k8.row.col.f32.tf32.tf32.f32 "
        "{%0,%1,%2,%3}, {%4,%5,%6,%7}, {%8,%9}, {%0,%1,%2,%3};"
        : "+f"(c[0]), "+f"(c[1]), "+f"(c[2]), "+f"(c[3])
        : "r"(a0), "r"(a1), "r"(a2), "r"(a3), "r"(b0), "r"(b1));
}

__device__ __forceinline__ void cp16(uint32_t dst, const void* src) {
    asm volatile("cp.async.ca.shared.global [%0], [%1], 16;" :: "r"(dst), "l"(src));
}
#define CP_COMMIT() asm volatile("cp.async.commit_group;" ::: "memory")
#define CP_WAIT0()  asm volatile("cp.async.wait_group 0;"  ::: "memory")

// ---------------------------------------------------------------------------
// tf32 mma.sync GEMM body (shared by QKV-fused and single variants).
// C[M,N] = A[M,K] * B[N,K]^T, CTA tile 128x128, BK=16, double-buffered smem.
// ---------------------------------------------------------------------------
__device__ __forceinline__ void gemm_body(const float* __restrict__ A,
                                          const float* __restrict__ B,
                                          float* __restrict__ C)
{
    __shared__ float As[2][128][20];
    __shared__ float Bs[2][128][20];

    const int tid = threadIdx.x;
    const int wid = tid >> 5;
    const int lid = tid & 31;
    const int g   = lid >> 2;
    const int tg  = lid & 3;
    const int mbase = (wid & 3) * 32;
    const int nbase = (wid >> 2) * 64;
    const int bm = blockIdx.y * 128;
    const int bn = blockIdx.x * 128;

    const float* Ap = A + (size_t)bm * GK;
    const float* Bp = B + (size_t)bn * GK;

    float c[2][8][4];
#pragma unroll
    for (int i = 0; i < 2; ++i)
#pragma unroll
        for (int j = 0; j < 8; ++j)
#pragma unroll
            for (int q = 0; q < 4; ++q) c[i][j][q] = 0.f;

    float4 ra[2], rb[2];

#pragma unroll
    for (int l = 0; l < 2; ++l) {
        const int idx = l * 256 + tid;
        const int m   = idx >> 2;
        const int kg  = (idx & 3) << 2;
        ra[l] = *(const float4*)(Ap + (size_t)m * GK + kg);
        rb[l] = *(const float4*)(Bp + (size_t)m * GK + kg);
    }
#pragma unroll
    for (int l = 0; l < 2; ++l) {
        const int idx = l * 256 + tid;
        const int m   = idx >> 2;
        const int kg  = (idx & 3) << 2;
        As[0][m][kg + 0] = tf32f(ra[l].x);
        As[0][m][kg + 1] = tf32f(ra[l].y);
        As[0][m][kg + 2] = tf32f(ra[l].z);
        As[0][m][kg + 3] = tf32f(ra[l].w);
        Bs[0][m][kg + 0] = tf32f(rb[l].x);
        Bs[0][m][kg + 1] = tf32f(rb[l].y);
        Bs[0][m][kg + 2] = tf32f(rb[l].z);
        Bs[0][m][kg + 3] = tf32f(rb[l].w);
    }
    __syncthreads();

    const int NIT = GK / 16;   // 128
    for (int it = 0; it < NIT; ++it) {
        const int p = it & 1;

        if (it + 1 < NIT) {
            const int k0 = (it + 1) * 16;
#pragma unroll
            for (int l = 0; l < 2; ++l) {
                const int idx = l * 256 + tid;
                const int m   = idx >> 2;
                const int kg  = (idx & 3) << 2;
                ra[l] = *(const float4*)(Ap + (size_t)m * GK + k0 + kg);
                rb[l] = *(const float4*)(Bp + (size_t)m * GK + k0 + kg);
            }
        }

#pragma unroll
        for (int ks = 0; ks < 2; ++ks) {
            const int kk = ks * 8;
            uint32_t af[2][4], bf[8][2];
#pragma unroll
            for (int mt = 0; mt < 2; ++mt) {
                const int r0 = mbase + mt * 16 + g;
                af[mt][0] = __float_as_uint(As[p][r0][kk + tg]);
                af[mt][1] = __float_as_uint(As[p][r0 + 8][kk + tg]);
                af[mt][2] = __float_as_uint(As[p][r0][kk + tg + 4]);
                af[mt][3] = __float_as_uint(As[p][r0 + 8][kk + tg + 4]);
            }
#pragma unroll
            for (int nt = 0; nt < 8; ++nt) {
                const int n0 = nbase + nt * 8 + g;
                bf[nt][0] = __float_as_uint(Bs[p][n0][kk + tg]);
                bf[nt][1] = __float_as_uint(Bs[p][n0][kk + tg + 4]);
            }
#pragma unroll
            for (int mt = 0; mt < 2; ++mt)
#pragma unroll
                for (int nt = 0; nt < 8; ++nt)
                    mma_tf32_16x8x8(c[mt][nt], af[mt][0], af[mt][1], af[mt][2], af[mt][3],
                                    bf[nt][0], bf[nt][1]);
        }

        if (it + 1 < NIT) {
            const int pn = p ^ 1;
#pragma unroll
            for (int l = 0; l < 2; ++l) {
                const int idx = l * 256 + tid;
                const int m   = idx >> 2;
                const int kg  = (idx & 3) << 2;
                As[pn][m][kg + 0] = tf32f(ra[l].x);
                As[pn][m][kg + 1] = tf32f(ra[l].y);
                As[pn][m][kg + 2] = tf32f(ra[l].z);
                As[pn][m][kg + 3] = tf32f(ra[l].w);
                Bs[pn][m][kg + 0] = tf32f(rb[l].x);
                Bs[pn][m][kg + 1] = tf32f(rb[l].y);
                Bs[pn][m][kg + 2] = tf32f(rb[l].z);
                Bs[pn][m][kg + 3] = tf32f(rb[l].w);
            }
            __syncthreads();
        }
    }

#pragma unroll
    for (int mt = 0; mt < 2; ++mt) {
        const int r0 = bm + mbase + mt * 16 + g;
#pragma unroll
        for (int nt = 0; nt < 8; ++nt) {
            const int cc = bn + nbase + nt * 8 + 2 * tg;
            *(float2*)(C + (size_t)r0 * GN + cc)       = make_float2(c[mt][nt][0], c[mt][nt][1]);
            *(float2*)(C + (size_t)(r0 + 8) * GN + cc) = make_float2(c[mt][nt][2], c[mt][nt][3]);
        }
    }
}

// fused QKV: blockIdx.z selects which weight/output
__global__ void __launch_bounds__(256) gemm_qkv(const float* __restrict__ X,
                                                const float* __restrict__ Wq,
                                                const float* __restrict__ Wk,
                                                const float* __restrict__ Wv,
                                                float* __restrict__ Qo,
                                                float* __restrict__ Ko,
                                                float* __restrict__ Vo)
{
    const int z = blockIdx.z;
    const float* B = (z == 0) ? Wq : (z == 1) ? Wk : Wv;
    float*       C = (z == 0) ? Qo : (z == 1) ? Ko : Vo;
    gemm_body(X, B, C);
}

__global__ void __launch_bounds__(256) gemm_tf32(const float* __restrict__ A,
                                                 const float* __restrict__ B,
                                                 float* __restrict__ C)
{
    gemm_body(A, B, C);
}

// ---------------------------------------------------------------------------
// RoPE in place on [B,S,H] with per-head dim 128 (half = 64).
// ---------------------------------------------------------------------------
__global__ void __launch_bounds__(256) rope_kernel(float* __restrict__ X)
{
    const int i  = blockIdx.x * blockDim.x + threadIdx.x;
    const int j  = i & 63;
    const int t  = i >> 6;
    const int h  = t & (NHEAD - 1);
    const int t2 = t >> 4;
    const int s  = t2 & (SEQ - 1);
    const int b  = t2 >> 11;

    float* p = X + ((size_t)(b * SEQ + s)) * HID + h * HDIM;

    const float invf = powf(10000.0f, -(float)j * (1.0f / 64.0f));
    const float ang  = (float)s * invf;
    float sn, cs;
    sincosf(ang, &sn, &cs);

    const float x1 = p[j];
    const float x2 = p[j + 64];
    p[j]      = x1 * cs - x2 * sn;
    p[j + 64] = x2 * cs + x1 * sn;
}

// ---------------------------------------------------------------------------
// Flash attention v2: tf32 mma, cp.async double-buffered K/V, register P.
// CTA: 128 q-rows of one (b,h); 8 warps x 16 rows. KV tile = 64.
// smem: Qs[128][132] tf32, Ks[2][64][132], Vs[2][64][136] (natural layouts).
// ---------------------------------------------------------------------------
#define PK  132
#define PVN 136

__global__ void __launch_bounds__(256) flash_mma(const float* __restrict__ Q,
                                                 const float* __restrict__ K,
                                                 const float* __restrict__ V,
                                                 float* __restrict__ O)
{
    extern __shared__ float smf[];
    float* Qs = smf;                     // 128*132
    float* Ks = Qs + 128 * PK;           // 2 * 64*132
    float* Vs = Ks + 2 * 64 * PK;        // 2 * 64*136

    const int tid = threadIdx.x;
    const int wid = tid >> 5;
    const int lid = tid & 31;
    const int g   = lid >> 2;
    const int tg  = lid & 3;
    const int r0  = wid * 16;
    const int q0  = blockIdx.x * 128;
    const size_t base = ((size_t)blockIdx.z * SEQ) * HID + (size_t)blockIdx.y * HDIM;

    const uint32_t ks_u32 = (uint32_t)__cvta_generic_to_shared(Ks);
    const uint32_t vs_u32 = (uint32_t)__cvta_generic_to_shared(Vs);

    // ---- load Q tile (tf32)
    for (int idx = tid; idx < 128 * 32; idx += 256) {
        const int m  = idx >> 5;
        const int dg = (idx & 31) << 2;
        float4 v = *(const float4*)(Q + base + (size_t)(q0 + m) * HID + dg);
        float* dst = &Qs[m * PK + dg];
        dst[0] = tf32f(v.x); dst[1] = tf32f(v.y);
        dst[2] = tf32f(v.z); dst[3] = tf32f(v.w);
    }

    // per-thread cp.async chunk coords (8 chunks of 16B each for K and V)
    // chunk l: row n = l*8 + (tid>>5)... derived: idx = l*256+tid; n = idx>>5; c = (idx&31)*4
    const int nkv = q0 / 64 + 2;

    // ---- prologue: async-load tile 0 into buffer 0
#pragma unroll
    for (int l = 0; l < 8; ++l) {
        const int idx = l * 256 + tid;
        const int n   = idx >> 5;
        const int c4  = (idx & 31) << 2;
        const size_t go = base + (size_t)n * HID + c4;
        cp16(ks_u32 + (uint32_t)(n * PK + c4) * 4,  K + go);
        cp16(vs_u32 + (uint32_t)(n * PVN + c4) * 4, V + go);
    }
    CP_COMMIT();

    float o[16][4];
#pragma unroll
    for (int i = 0; i < 16; ++i)
#pragma unroll
        for (int j = 0; j < 4; ++j) o[i][j] = 0.f;
    float mrow[2] = {-1e30f, -1e30f};
    float lrow[2] = {0.f, 0.f};

    const float scale = 0.08838834764831845f;   // 1/sqrt(128)
    const int lane_lo = (lid & ~3) | (tg >> 1);
    const int lane_hi = lane_lo + 2;

    for (int kt = 0; kt < nkv; ++kt) {
        const int p = kt & 1;
        float* Kp_s = Ks + p * 64 * PK;
        float* Vp_s = Vs + p * 64 * PVN;

        CP_WAIT0();
        __syncthreads();          // buffer p fully arrived for everyone

        // ---- issue async loads for next tile into buffer p^1
        if (kt + 1 < nkv) {
            const int kv1 = (kt + 1) * 64;
            const uint32_t kb = ks_u32 + (uint32_t)((p ^ 1) * 64 * PK) * 4;
            const uint32_t vb = vs_u32 + (uint32_t)((p ^ 1) * 64 * PVN) * 4;
#pragma unroll
            for (int l = 0; l < 8; ++l) {
                const int idx = l * 256 + tid;
                const int n   = idx >> 5;
                const int c4  = (idx & 31) << 2;
                const size_t go = base + (size_t)(kv1 + n) * HID + c4;
                cp16(kb + (uint32_t)(n * PK + c4) * 4,  K + go);
                cp16(vb + (uint32_t)(n * PVN + c4) * 4, V + go);
            }
        }
        CP_COMMIT();

        // ---- convert K[p], V[p] to tf32 in place (own chunks)
#pragma unroll
        for (int l = 0; l < 8; ++l) {
            const int idx = l * 256 + tid;
            const int n   = idx >> 5;
            const int c4  = (idx & 31) << 2;
            float4* ka = (float4*)&Kp_s[n * PK + c4];
            float4 kv = *ka;
            kv.x = tf32f(kv.x); kv.y = tf32f(kv.y);
            kv.z = tf32f(kv.z); kv.w = tf32f(kv.w);
            *ka = kv;
            float4* va = (float4*)&Vp_s[n * PVN + c4];
            float4 vv = *va;
            vv.x = tf32f(vv.x); vv.y = tf32f(vv.y);
            vv.z = tf32f(vv.z); vv.w = tf32f(vv.w);
            *va = vv;
        }
        __syncthreads();          // converted tiles visible to all warps

        // ---- S = Q K^T  (warp rows r0..r0+15, cols 0..63)
        float s[8][4];
#pragma unroll
        for (int nt = 0; nt < 8; ++nt)
#pragma unroll
            for (int j = 0; j < 4; ++j) s[nt][j] = 0.f;

#pragma unroll
        for (int ks = 0; ks < 16; ++ks) {
            const int kk = ks * 8;
            const uint32_t a0 = __float_as_uint(Qs[(r0 + g) * PK + kk + tg]);
            const uint32_t a1 = __float_as_uint(Qs[(r0 + g + 8) * PK + kk + tg]);
            const uint32_t a2 = __float_as_uint(Qs[(r0 + g) * PK + kk + tg + 4]);
            const uint32_t a3 = __float_as_uint(Qs[(r0 + g + 8) * PK + kk + tg + 4]);
#pragma unroll
            for (int nt = 0; nt < 8; ++nt) {
                const uint32_t b0 = __float_as_uint(Kp_s[(nt * 8 + g) * PK + kk + tg]);
                const uint32_t b1 = __float_as_uint(Kp_s[(nt * 8 + g) * PK + kk + tg + 4]);
                mma_tf32_16x8x8(s[nt], a0, a1, a2, a3, b0, b1);
            }
        }

        // ---- online softmax on fragments; P stays in s[][] (tf32-rounded)
        const int kv0 = kt * 64;
        const bool needm = (kv0 + 63 > q0 + r0);
#pragma unroll
        for (int i = 0; i < 2; ++i) {
            const int rg = q0 + r0 + g + 8 * i;
            float lm = -1e30f;
#pragma unroll
            for (int nt = 0; nt < 8; ++nt) {
                float va = s[nt][2 * i] * scale;
                float vb = s[nt][2 * i + 1] * scale;
                if (needm) {
                    const int c0 = kv0 + nt * 8 + 2 * tg;
                    if (c0 > rg)     va = -1e30f;
                    if (c0 + 1 > rg) vb = -1e30f;
                }
                s[nt][2 * i]     = va;
                s[nt][2 * i + 1] = vb;
                lm = fmaxf(lm, fmaxf(va, vb));
            }
            lm = fmaxf(lm, __shfl_xor_sync(0xffffffffu, lm, 1));
            lm = fmaxf(lm, __shfl_xor_sync(0xffffffffu, lm, 2));

            const float mn = fmaxf(mrow[i], lm);
            const float sc = __expf(mrow[i] - mn);
            float ps = 0.f;
#pragma unroll
            for (int nt = 0; nt < 8; ++nt) {
                const float p0 = tf32f(__expf(s[nt][2 * i] - mn));
                const float p1 = tf32f(__expf(s[nt][2 * i + 1] - mn));
                s[nt][2 * i]     = p0;
                s[nt][2 * i + 1] = p1;
                ps += p0 + p1;
            }
            ps += __shfl_xor_sync(0xffffffffu, ps, 1);
            ps += __shfl_xor_sync(0xffffffffu, ps, 2);

            lrow[i] = lrow[i] * sc + ps;
            mrow[i] = mn;
#pragma unroll
            for (int nt = 0; nt < 16; ++nt) {
                o[nt][2 * i]     *= sc;
                o[nt][2 * i + 1] *= sc;
            }
        }

        // ---- O += P V : A-fragments from registers via quad shuffles
#pragma unroll
        for (int ks = 0; ks < 8; ++ks) {
            const float x0 = __shfl_sync(0xffffffffu, s[ks][0], lane_lo);
            const float x1 = __shfl_sync(0xffffffffu, s[ks][1], lane_lo);
            const float y0 = __shfl_sync(0xffffffffu, s[ks][2], lane_lo);
            const float y1 = __shfl_sync(0xffffffffu, s[ks][3], lane_lo);
            const float z0 = __shfl_sync(0xffffffffu, s[ks][0], lane_hi);
            const float z1 = __shfl_sync(0xffffffffu, s[ks][1], lane_hi);
            const float w0 = __shfl_sync(0xffffffffu, s[ks][2], lane_hi);
            const float w1 = __shfl_sync(0xffffffffu, s[ks][3], lane_hi);
            const bool odd = (tg & 1);
            const uint32_t a0 = __float_as_uint(odd ? x1 : x0);
            const uint32_t a1 = __float_as_uint(odd ? y1 : y0);
            const uint32_t a2 = __float_as_uint(odd ? z1 : z0);
            const uint32_t a3 = __float_as_uint(odd ? w1 : w0);
            const int kk = ks * 8;
#pragma unroll
            for (int nt = 0; nt < 16; ++nt) {
                const uint32_t b0 = __float_as_uint(Vp_s[(kk + tg) * PVN + nt * 8 + g]);
                const uint32_t b1 = __float_as_uint(Vp_s[(kk + tg + 4) * PVN + nt * 8 + g]);
                mma_tf32_16x8x8(o[nt], a0, a1, a2, a3, b0, b1);
            }
        }
        // no sync here: next iteration's wait+sync guards buffer reuse
    }

    // ---- epilogue: normalize, store
    const float inv0 = 1.0f / lrow[0];
    const float inv1 = 1.0f / lrow[1];
#pragma unroll
    for (int nt = 0; nt < 16; ++nt) {
        const int col = nt * 8 + 2 * tg;
        *(float2*)(O + base + (size_t)(q0 + r0 + g) * HID + col) =
            make_float2(o[nt][0] * inv0, o[nt][1] * inv0);
        *(float2*)(O + base + (size_t)(q0 + r0 + g + 8) * HID + col) =
            make_float2(o[nt][2] * inv1, o[nt][3] * inv1);
    }
}

// ---------------------------------------------------------------------------
extern "C" void kernel_launch(void* const* d_in, const int* in_sizes, int n_in,
                              void* d_out, int out_size)
{
    const float* X  = (const float*)d_in[0];
    // d_in[1] = attention_mask (causal; implemented analytically, unused)
    const float* Wq = (const float*)d_in[2];
    const float* Wk = (const float*)d_in[3];
    const float* Wv = (const float*)d_in[4];
    const float* Wo = (const float*)d_in[5];
    float* out = (float*)d_out;

    float *Qp, *Kp, *Vp, *Op;
    cudaGetSymbolAddress((void**)&Qp, g_Q);
    cudaGetSymbolAddress((void**)&Kp, g_K);
    cudaGetSymbolAddress((void**)&Vp, g_V);
    cudaGetSymbolAddress((void**)&Op, g_O);

    const int smem_flash = (128 * PK + 2 * 64 * PK + 2 * 64 * PVN) * 4; // 204800
    cudaFuncSetAttribute(flash_mma,
                         cudaFuncAttributeMaxDynamicSharedMemorySize, smem_flash);

    dim3 gq(GN / 128, MROWS / 128, 3);   // fused QKV
    gemm_qkv<<<gq, 256>>>(X, Wq, Wk, Wv, Qp, Kp, Vp);

    const int rope_total = BSZ * SEQ * NHEAD * 64;
    rope_kernel<<<rope_total / 256, 256>>>(Qp);
    rope_kernel<<<rope_total / 256, 256>>>(Kp);

    flash_mma<<<dim3(SEQ / 128, NHEAD, BSZ), 256, smem_flash>>>(Qp, Kp, Vp, Op);

    dim3 gg(GN / 128, MROWS / 128);
    gemm_tf32<<<gg, 256>>>(Op, Wo, out);
}